// round 14
// baseline (speedup 1.0000x reference)
#include <cuda_runtime.h>
#include <cuda_fp16.h>
#include <mma.h>
#include <cstdint>

using namespace nvcuda;

#define NN 100000
#define NE 600000
#define D  128
#define CAP 64

// ---------------- device scratch ----------------
__device__ int    g_cnt[NN];                    // zero-init; self-cleaned by fused_kernel
__device__ uint2  g_bucket[(size_t)NN * CAP];   // (src, weight_bits)
__device__ __half g_wt[2 * D * D];              // fp16 [Wl ; Wr]  (K-row major [256][128])

// ---------------- cp.async helpers ----------------
__device__ __forceinline__ void cp_async16(uint32_t dst, const void* src) {
    asm volatile("cp.async.cg.shared.global [%0], [%1], 16;"
                 :: "r"(dst), "l"(src) : "memory");
}
#define CP_COMMIT() asm volatile("cp.async.commit_group;" ::: "memory")
#define CP_WAIT(n)  asm volatile("cp.async.wait_group %0;" :: "n"(n) : "memory")

// ---------------- scatter edges into buckets (+ weight conversion) ----------
__global__ void __launch_bounds__(256) scatter_kernel(
    const int* __restrict__ esrc,
    const int* __restrict__ edst,
    const float* __restrict__ ew,
    const float* __restrict__ wl,
    const float* __restrict__ wr)
{
    // first 64 blocks also convert weights to fp16 (g_wt only read by fused_kernel)
    if (blockIdx.x < 64) {
        int i = blockIdx.x * 256 + threadIdx.x;   // 0..16383
        g_wt[i]         = __float2half_rn(wl[i]);
        g_wt[D * D + i] = __float2half_rn(wr[i]);
    }
    int e = blockIdx.x * 256 + threadIdx.x;
    if (e >= NE) return;
    int s = __ldg(&esrc[e]);
    int d = __ldg(&edst[e]);
    float w = __ldg(&ew[e]);
    int pos = atomicAdd(&g_cnt[d], 1);
    g_bucket[(size_t)d * CAP + pos] = make_uint2((unsigned)s, __float_as_uint(w));
}

// ---------------- fused gather + dual fp16 GEMM (B smem-resident) -------------
// out[tile] = agg(tile) @ Wl + x(tile) @ Wr + (bl+br)
#define BM 128
#define LDA 136     // halves
#define LDB 136     // halves
#define LDBI 136    // floats

// smem byte offsets
#define OFF_AS   0
#define OFF_B    (BM * LDA * 2)                      // 34816
#define OFF_BIAS (OFF_B + 256 * LDB * 2)             // +69632 = 104448
#define SM_BYTES (OFF_BIAS + 16 * LDBI * 4)          // +8704  = 113152

__global__ void __launch_bounds__(256, 2) fused_kernel(
    const float* __restrict__ x,
    const float* __restrict__ bl,
    const float* __restrict__ br,
    float* __restrict__ out)
{
    extern __shared__ char smraw[];
    __half (*As)[LDA] = (__half(*)[LDA])(smraw + OFF_AS);
    __half* Bsm  = (__half*)(smraw + OFF_B);     // [256][LDB]
    float*  Bias = (float*) (smraw + OFF_BIAS);  // [16][LDBI]

    const int tid = threadIdx.x;
    const int wid = tid >> 5;
    const int lane = tid & 31;
    const int warp_m = wid & 3;    // 32-row group
    const int warp_n = wid >> 2;   // 64-col group
    const int m0 = blockIdx.x * BM;
    const bool swap = ((blockIdx.x / 148) & 1) != 0;   // wave-parity phase offset

    // ---- issue the ENTIRE B load (64KB); first fill phase hides it ----
    {
        uint32_t b_base = (uint32_t)__cvta_generic_to_shared(Bsm);
        const int c8 = (tid & 15) * 8;
        const int r0 = tid >> 4;
        #pragma unroll
        for (int it = 0; it < 16; it++) {
            int row = r0 + it * 16;
            cp_async16(b_base + (row * LDB + c8) * 2,
                       &g_wt[(size_t)row * D + c8]);
        }
        CP_COMMIT();
    }

    // ---- bias replica tile (fp32) ----
    for (int s = tid; s < 16 * LDBI; s += 256) {
        int c = s % LDBI;
        Bias[s] = (c < 128) ? (bl[c] + br[c]) : 0.f;
    }

    // ---- gather agg rows into As (R8 serial loop; self-cleans g_cnt) ----
    auto fill_agg = [&]() {
        int node_row = wid * 16;
        for (int i = 0; i < 16; i++) {
            int row = node_row + i;
            int n = m0 + row;
            float4 a = make_float4(0.f, 0.f, 0.f, 0.f);
            if (n < NN) {
                int deg = __ldg(&g_cnt[n]);
                if (lane == 0) g_cnt[n] = 0;       // self-clean for next replay
                const uint2* bk = &g_bucket[(size_t)n * CAP];
                for (int j = 0; j < deg; j++) {
                    uint2 ent = __ldg(&bk[j]);
                    float w = __uint_as_float(ent.y);
                    float4 v = *(const float4*)&x[(size_t)ent.x * D + lane * 4];
                    a.x += w * v.x; a.y += w * v.y; a.z += w * v.z; a.w += w * v.w;
                }
            }
            __half2* dst = (__half2*)&As[row][lane * 4];
            dst[0] = __floats2half2_rn(a.x, a.y);
            dst[1] = __floats2half2_rn(a.z, a.w);
        }
    };

    // ---- fill As with this CTA's x rows (fp16) ----
    auto fill_x = [&]() {
        #pragma unroll
        for (int it = 0; it < 8; it++) {
            int slot = tid + it * 256;        // 0..2047
            int row = slot >> 4;              // 0..127
            int c8  = (slot & 15) * 8;        // 0..120
            int gr = m0 + row;
            float4 v0 = make_float4(0.f, 0.f, 0.f, 0.f), v1 = v0;
            if (gr < NN) {
                v0 = *(const float4*)&x[(size_t)gr * D + c8];
                v1 = *(const float4*)&x[(size_t)gr * D + c8 + 4];
            }
            __half2 h[4];
            h[0] = __floats2half2_rn(v0.x, v0.y);
            h[1] = __floats2half2_rn(v0.z, v0.w);
            h[2] = __floats2half2_rn(v1.x, v1.y);
            h[3] = __floats2half2_rn(v1.z, v1.w);
            *(uint4*)&As[row][c8] = *(uint4*)h;
        }
    };

    wmma::fragment<wmma::accumulator, 16, 16, 16, float> acc[2][4];

    // ---- GEMM over one K-half: no barriers, no waits ----
    auto gemm_half = [&](int kbase) {
        #pragma unroll
        for (int kc = 0; kc < 8; kc++) {
            wmma::fragment<wmma::matrix_a, 16, 16, 16, __half, wmma::row_major> af[2];
            #pragma unroll
            for (int i = 0; i < 2; i++)
                wmma::load_matrix_sync(af[i], &As[warp_m * 32 + i * 16][kc * 16], LDA);
            #pragma unroll
            for (int j = 0; j < 4; j++) {
                wmma::fragment<wmma::matrix_b, 16, 16, 16, __half, wmma::row_major> bf;
                wmma::load_matrix_sync(bf,
                    &Bsm[(size_t)(kbase + kc * 16) * LDB + warp_n * 64 + j * 16], LDB);
                #pragma unroll
                for (int i = 0; i < 2; i++)
                    wmma::mma_sync(acc[i][j], af[i], bf, acc[i][j]);
            }
        }
    };

    // ---- phase 1 fill (even waves: gather; odd waves: x rows) ----
    if (!swap) fill_agg(); else fill_x();
    CP_WAIT(0);          // B resident
    __syncthreads();     // As + B + Bias visible

    // ---- init accumulators from bias ----
    #pragma unroll
    for (int i = 0; i < 2; i++)
        #pragma unroll
        for (int j = 0; j < 4; j++)
            wmma::load_matrix_sync(acc[i][j], &Bias[warp_n * 64 + j * 16], LDBI,
                                   wmma::mem_row_major);

    // ---- GEMM 1 ----
    gemm_half(swap ? 128 : 0);

    // ---- phase 2 fill (the other operand) ----
    __syncthreads();
    if (!swap) fill_x(); else fill_agg();
    __syncthreads();

    // ---- GEMM 2 ----
    gemm_half(swap ? 0 : 128);

    // ---- epilogue (NN % 16 == 0 -> tiles fully in or out) ----
    #pragma unroll
    for (int i = 0; i < 2; i++) {
        int row0 = m0 + warp_m * 32 + i * 16;
        if (row0 >= NN) continue;
        #pragma unroll
        for (int j = 0; j < 4; j++) {
            int col0 = warp_n * 64 + j * 16;
            wmma::store_matrix_sync(&out[(size_t)row0 * D + col0], acc[i][j], D,
                                    wmma::mem_row_major);
        }
    }
}

// ---------------- launch ----------------
extern "C" void kernel_launch(void* const* d_in, const int* in_sizes, int n_in,
                              void* d_out, int out_size)
{
    const float* x    = (const float*)d_in[0];
    const int*   esrc = (const int*)  d_in[1];
    const int*   edst = (const int*)  d_in[2];
    const float* ew   = (const float*)d_in[3];
    const float* wl   = (const float*)d_in[4];
    const float* bl   = (const float*)d_in[5];
    const float* wr   = (const float*)d_in[6];
    const float* br   = (const float*)d_in[7];
    float* out = (float*)d_out;

    static bool attr_set = false;
    if (!attr_set) {
        cudaFuncSetAttribute(fused_kernel,
                             cudaFuncAttributeMaxDynamicSharedMemorySize, SM_BYTES);
        attr_set = true;
    }

    scatter_kernel<<<(NE + 255) / 256, 256>>>(esrc, edst, ew, wl, wr);
    fused_kernel<<<(NN + BM - 1) / BM, 256, SM_BYTES>>>(x, bl, br, out);
}

// round 15
// speedup vs baseline: 1.1623x; 1.1623x over previous
#include <cuda_runtime.h>
#include <cuda_fp16.h>
#include <mma.h>
#include <cstdint>

using namespace nvcuda;

#define NN 100000
#define NE 600000
#define D  128
#define CAP 64

// ---------------- device scratch ----------------
__device__ int    g_cnt[NN];                    // zero-init; self-cleaned by gather
__device__ uint2  g_bucket[(size_t)NN * CAP];   // (src, weight_bits)
__device__ __half g_wt[2 * D * D];              // fp16 [Wl ; Wr]  (K-major [256][128])
__device__ __half g_a16[(size_t)NN * 256];      // [agg fp16 | x fp16] per node

// ---------------- cp.async helpers ----------------
__device__ __forceinline__ void cp_async16(uint32_t dst, const void* src) {
    asm volatile("cp.async.cg.shared.global [%0], [%1], 16;"
                 :: "r"(dst), "l"(src) : "memory");
}
__device__ __forceinline__ void cp_async16z(uint32_t dst, const void* src, uint32_t bytes) {
    asm volatile("cp.async.cg.shared.global [%0], [%1], 16, %2;"
                 :: "r"(dst), "l"(src), "r"(bytes) : "memory");
}
#define CP_COMMIT() asm volatile("cp.async.commit_group;" ::: "memory")
#define CP_WAIT(n)  asm volatile("cp.async.wait_group %0;" :: "n"(n) : "memory")

// ---------------- scatter edges into buckets (+ weight conversion) ----------
__global__ void __launch_bounds__(256) scatter_kernel(
    const int* __restrict__ esrc,
    const int* __restrict__ edst,
    const float* __restrict__ ew,
    const float* __restrict__ wl,
    const float* __restrict__ wr)
{
    if (blockIdx.x < 64) {
        int i = blockIdx.x * 256 + threadIdx.x;   // 0..16383
        g_wt[i]         = __float2half_rn(wl[i]);
        g_wt[D * D + i] = __float2half_rn(wr[i]);
    }
    int e = blockIdx.x * 256 + threadIdx.x;
    if (e >= NE) return;
    int s = __ldg(&esrc[e]);
    int d = __ldg(&edst[e]);
    float w = __ldg(&ew[e]);
    int pos = atomicAdd(&g_cnt[d], 1);
    g_bucket[(size_t)d * CAP + pos] = make_uint2((unsigned)s, __float_as_uint(w));
}

// ---------------- gather: warp per node -> g_a16 = [fp16(agg) | fp16(x)] ------
__global__ void __launch_bounds__(256) gather_kernel(const float* __restrict__ x)
{
    int n = blockIdx.x * 8 + (threadIdx.x >> 5);
    if (n >= NN) return;
    int lane = threadIdx.x & 31;

    int deg = __ldg(&g_cnt[n]);
    if (lane == 0) g_cnt[n] = 0;                 // self-clean for next replay

    float4 xv = *(const float4*)&x[(size_t)n * D + lane * 4];
    float4 a = make_float4(0.f, 0.f, 0.f, 0.f);
    const uint2* bk = &g_bucket[(size_t)n * CAP];
    for (int j = 0; j < deg; j++) {
        uint2 ent = __ldg(&bk[j]);
        float w = __uint_as_float(ent.y);
        float4 v = *(const float4*)&x[(size_t)ent.x * D + lane * 4];
        a.x += w * v.x; a.y += w * v.y; a.z += w * v.z; a.w += w * v.w;
    }

    __half2 ha0 = __floats2half2_rn(a.x, a.y);
    __half2 ha1 = __floats2half2_rn(a.z, a.w);
    __half2 hx0 = __floats2half2_rn(xv.x, xv.y);
    __half2 hx1 = __floats2half2_rn(xv.z, xv.w);
    __half2* dst = (__half2*)&g_a16[(size_t)n * 256 + lane * 4];
    dst[0] = ha0; dst[1] = ha1;
    __half2* dst2 = (__half2*)&g_a16[(size_t)n * 256 + 128 + lane * 4];
    dst2[0] = hx0; dst2[1] = hx1;
}

// ---------------- GEMM: out = g_a16[128x256] @ [Wl;Wr] + (bl+br) --------------
#define BM 128
#define LDA2 40      // halves per A-chunk row (32 + pad)
#define LDB 136
#define LDBI 136

// smem byte offsets
#define OFF_A    0                                   // [2][128][LDA2] half = 20480
#define OFF_B    20480                               // [256][LDB]    half = 69632
#define OFF_BIAS 90112                               // [16][LDBI]    f32  = 8704
#define SM_BYTES 98816

__global__ void __launch_bounds__(256, 2) gemm_kernel(
    const float* __restrict__ bl,
    const float* __restrict__ br,
    float* __restrict__ out)
{
    extern __shared__ char smraw[];
    __half* As2  = (__half*)(smraw + OFF_A);     // [2][128][LDA2]
    __half* Bsm  = (__half*)(smraw + OFF_B);     // [256][LDB]
    float*  Bias = (float*) (smraw + OFF_BIAS);  // [16][LDBI]

    const int tid = threadIdx.x;
    const int wid = tid >> 5;
    const int warp_m = wid & 3;
    const int warp_n = wid >> 2;
    const int m0 = blockIdx.x * BM;

    // ---- group 1: resident B (64KB) ----
    {
        uint32_t b_base = (uint32_t)__cvta_generic_to_shared(Bsm);
        const int c8 = (tid & 15) * 8;
        const int r0 = tid >> 4;
        #pragma unroll
        for (int it = 0; it < 16; it++) {
            int row = r0 + it * 16;
            cp_async16(b_base + (row * LDB + c8) * 2,
                       &g_wt[(size_t)row * D + c8]);
        }
        CP_COMMIT();
    }

    // ---- A chunk loader: [128 rows x 32 halves] at k-offset kc*32 ----
    uint32_t a_base = (uint32_t)__cvta_generic_to_shared(As2);
    auto issue_a = [&](int kc, int buf) {
        #pragma unroll
        for (int it = 0; it < 2; it++) {
            int slot = tid + it * 256;        // 0..511
            int row  = slot >> 2;             // 0..127
            int c8   = (slot & 3) * 8;        // halves 0,8,16,24
            int gr   = m0 + row;
            const __half* src = &g_a16[(size_t)(gr < NN ? gr : 0) * 256 + kc * 32 + c8];
            uint32_t bytes = (gr < NN) ? 16u : 0u;
            cp_async16z(a_base + (buf * BM * LDA2 + row * LDA2 + c8) * 2, src, bytes);
        }
        CP_COMMIT();
    };

    issue_a(0, 0);

    // ---- bias replica tile ----
    for (int s = tid; s < 16 * LDBI; s += 256) {
        int c = s % LDBI;
        Bias[s] = (c < 128) ? (bl[c] + br[c]) : 0.f;
    }
    __syncthreads();   // Bias visible

    wmma::fragment<wmma::accumulator, 16, 16, 16, float> acc[2][4];
    #pragma unroll
    for (int i = 0; i < 2; i++)
        #pragma unroll
        for (int j = 0; j < 4; j++)
            wmma::load_matrix_sync(acc[i][j], &Bias[warp_n * 64 + j * 16], LDBI,
                                   wmma::mem_row_major);

    // ---- main loop over 8 K-chunks of 32 ----
    for (int kc = 0; kc < 8; kc++) {
        int buf = kc & 1;
        if (kc < 7) { issue_a(kc + 1, buf ^ 1); CP_WAIT(1); }
        else        { CP_WAIT(0); }
        __syncthreads();

        #pragma unroll
        for (int kf = 0; kf < 2; kf++) {
            wmma::fragment<wmma::matrix_a, 16, 16, 16, __half, wmma::row_major> af[2];
            #pragma unroll
            for (int i = 0; i < 2; i++)
                wmma::load_matrix_sync(af[i],
                    &As2[buf * BM * LDA2 + (warp_m * 32 + i * 16) * LDA2 + kf * 16], LDA2);
            #pragma unroll
            for (int j = 0; j < 4; j++) {
                wmma::fragment<wmma::matrix_b, 16, 16, 16, __half, wmma::row_major> bf;
                wmma::load_matrix_sync(bf,
                    &Bsm[(size_t)(kc * 32 + kf * 16) * LDB + warp_n * 64 + j * 16], LDB);
                #pragma unroll
                for (int i = 0; i < 2; i++)
                    wmma::mma_sync(acc[i][j], af[i], bf, acc[i][j]);
            }
        }
        __syncthreads();
    }

    // ---- epilogue (NN % 16 == 0 -> tiles fully in or out) ----
    #pragma unroll
    for (int i = 0; i < 2; i++) {
        int row0 = m0 + warp_m * 32 + i * 16;
        if (row0 >= NN) continue;
        #pragma unroll
        for (int j = 0; j < 4; j++) {
            int col0 = warp_n * 64 + j * 16;
            wmma::store_matrix_sync(&out[(size_t)row0 * D + col0], acc[i][j], D,
                                    wmma::mem_row_major);
        }
    }
}

// ---------------- launch ----------------
extern "C" void kernel_launch(void* const* d_in, const int* in_sizes, int n_in,
                              void* d_out, int out_size)
{
    const float* x    = (const float*)d_in[0];
    const int*   esrc = (const int*)  d_in[1];
    const int*   edst = (const int*)  d_in[2];
    const float* ew   = (const float*)d_in[3];
    const float* wl   = (const float*)d_in[4];
    const float* bl   = (const float*)d_in[5];
    const float* wr   = (const float*)d_in[6];
    const float* br   = (const float*)d_in[7];
    float* out = (float*)d_out;

    static bool attr_set = false;
    if (!attr_set) {
        cudaFuncSetAttribute(gemm_kernel,
                             cudaFuncAttributeMaxDynamicSharedMemorySize, SM_BYTES);
        attr_set = true;
    }

    scatter_kernel<<<(NE + 255) / 256, 256>>>(esrc, edst, ew, wl, wr);
    gather_kernel<<<(NN + 7) / 8, 256>>>(x);
    gemm_kernel<<<(NN + BM - 1) / BM, 256, SM_BYTES>>>(bl, br, out);
}